// round 10
// baseline (speedup 1.0000x reference)
#include <cuda_runtime.h>
#include <cuda_bf16.h>
#include <cstdint>

// ---------------------------------------------------------------------------
// MTL2d_DeepSVDD: 3x (conv s2 + relu -> MHSA(relpos bias) + residual) -> pool -> linear
// B=32, heads=3, dims {16,32,64}, dh {5,10,21}, inner {15,30,63}, N {1024,256,64}
// 10 launches: conv1,proj1,attn1,outproj1, conv2,proj2,attn2,outproj2, conv3, stage3_fused
// ---------------------------------------------------------------------------

#define BATCH 32
#define HEADS 3

__device__ float g_z1[BATCH * 16 * 32 * 32];
__device__ float g_z2[BATCH * 32 * 16 * 16];
__device__ float g_z3[BATCH * 64 * 8 * 8];
__device__ float g_qkv[BATCH * 45 * 1024];
__device__ float g_att[BATCH * 15 * 1024];

// ---------------- packed f32x2 helpers --------------------------------------
__device__ __forceinline__ unsigned long long pk2(float x, float y) {
    unsigned long long r;
    asm("mov.b64 %0, {%1, %2};" : "=l"(r) : "f"(x), "f"(y));
    return r;
}
__device__ __forceinline__ void upk2(unsigned long long v, float& x, float& y) {
    asm("mov.b64 {%0, %1}, %2;" : "=f"(x), "=f"(y) : "l"(v));
}
__device__ __forceinline__ unsigned long long fma2(unsigned long long a,
                                                   unsigned long long b,
                                                   unsigned long long c) {
    unsigned long long d;
    asm("fma.rn.f32x2 %0, %1, %2, %3;" : "=l"(d) : "l"(a), "l"(b), "l"(c));
    return d;
}
__device__ __forceinline__ unsigned long long add2(unsigned long long a,
                                                   unsigned long long b) {
    unsigned long long d;
    asm("add.rn.f32x2 %0, %1, %2;" : "=l"(d) : "l"(a), "l"(b));
    return d;
}
__device__ __forceinline__ float ex2f(float x) {
    float y;
    asm("ex2.approx.ftz.f32 %0, %1;" : "=f"(y) : "f"(x));
    return y;
}

// ---------------------------------------------------------------------------
// conv 3x3 stride-2 pad-1 + bias + relu, v3: CPT channels x OXPT pixels per
// thread (CPT=2 -> 2-4x more blocks than v2 for the deep stages).
// Weights repacked [ci*9+k][co] in smem; packed fma2.
// ---------------------------------------------------------------------------
template<int CIN, int COUT, int HIN, int HOUT, int CPT, int OXPT>
__global__ void __launch_bounds__(256)
conv_v3(const float* __restrict__ x,
        const float* __restrict__ w,
        const float* __restrict__ bias,
        float* __restrict__ y) {
    extern __shared__ float sw[];   // [(CIN*9)][COUT]
    int tid = threadIdx.x;
    for (int i = tid; i < COUT * CIN * 9; i += 256) {
        int co = i / (CIN * 9);
        int r  = i % (CIN * 9);
        sw[r * COUT + co] = w[i];
    }
    __syncthreads();

    constexpr int OXG = HOUT / OXPT;
    constexpr int NCG = COUT / CPT;
    constexpr int NP  = CPT / 2;
    constexpr int NX  = 2 * OXPT + 1;

    int idx = blockIdx.x * 256 + tid;
    int oxp = idx % OXG;
    int t   = idx / OXG;
    int oy  = t % HOUT; t /= HOUT;
    int cog = t % NCG;
    int b   = t / NCG;

    int c0  = cog * CPT;
    int ox0 = oxp * OXPT;
    const float* xb = x + (size_t)b * CIN * HIN * HIN;

    unsigned long long acc[OXPT][NP];
    #pragma unroll
    for (int u = 0; u < OXPT; u++)
        #pragma unroll
        for (int p = 0; p < NP; p++)
            acc[u][p] = pk2(bias[c0 + 2 * p], bias[c0 + 2 * p + 1]);

    int ixb = ox0 * 2 - 1;

    for (int ci = 0; ci < CIN; ci++) {
        #pragma unroll
        for (int ky = 0; ky < 3; ky++) {
            int iy = oy * 2 - 1 + ky;
            if ((unsigned)iy >= (unsigned)HIN) continue;
            const float* row = xb + (ci * HIN + iy) * HIN;
            float xv[NX];
            #pragma unroll
            for (int u = 0; u < NX; u++) {
                int ix = ixb + u;
                xv[u] = ((unsigned)ix < (unsigned)HIN) ? row[ix] : 0.0f;
            }
            const float* wp = &sw[(ci * 9 + ky * 3) * COUT + c0];
            #pragma unroll
            for (int kx = 0; kx < 3; kx++) {
                #pragma unroll
                for (int p = 0; p < NP; p++) {
                    unsigned long long wv = *(const unsigned long long*)(wp + kx * COUT + 2 * p);
                    #pragma unroll
                    for (int u = 0; u < OXPT; u++) {
                        unsigned long long x2 = pk2(xv[kx + 2 * u], xv[kx + 2 * u]);
                        acc[u][p] = fma2(x2, wv, acc[u][p]);
                    }
                }
            }
        }
    }

    float vch[CPT][OXPT];
    #pragma unroll
    for (int u = 0; u < OXPT; u++)
        #pragma unroll
        for (int p = 0; p < NP; p++)
            upk2(acc[u][p], vch[2 * p][u], vch[2 * p + 1][u]);

    #pragma unroll
    for (int r = 0; r < CPT; r++) {
        size_t o = (((size_t)b * COUT + c0 + r) * HOUT + oy) * HOUT + ox0;
        if (OXPT == 2) {
            float2 st2 = make_float2(fmaxf(vch[r][0], 0.0f), fmaxf(vch[r][1], 0.0f));
            *(float2*)(y + o) = st2;
        } else {
            y[o] = fmaxf(vch[r][0], 0.0f);
        }
    }
}

// ---------------------------------------------------------------------------
// 1x1 projection, float4-vectorized along n
// ---------------------------------------------------------------------------
template<int C, int O, int N>
__global__ void proj1x1(const float* __restrict__ z,
                        const float* __restrict__ w,
                        const float* __restrict__ bias,
                        float* __restrict__ y) {
    int idx = blockIdx.x * blockDim.x + threadIdx.x;
    constexpr int N4 = N / 4;
    constexpr int TOTAL4 = BATCH * O * N4;
    if (idx >= TOTAL4) return;
    int n4 = idx % N4;
    int t  = idx / N4;
    int o = t % O;
    int b = t / O;
    float bo = bias[o];
    float4 s = make_float4(bo, bo, bo, bo);
    const float4* zb = (const float4*)(z + (size_t)b * C * N);
    const float* wr = w + (size_t)o * C;
    #pragma unroll
    for (int c = 0; c < C; c++) {
        float wv = wr[c];
        float4 zv = zb[c * N4 + n4];
        s.x += wv * zv.x; s.y += wv * zv.y; s.z += wv * zv.z; s.w += wv * zv.w;
    }
    ((float4*)y)[idx] = s;
}

// ---------------------------------------------------------------------------
// flash attention, NO-MAX single-pass softmax (scores provably tiny for this
// model; exp2 without max-subtraction is exact softmax here).
// block = (b, h, q-slice). K,V + de-headed pre-scaled bias table in SMEM.
// ---------------------------------------------------------------------------
template<int N, int D, int HH, int QBLK, int TQ>
__global__ void __launch_bounds__(256, 2)
attn_flash(const float* __restrict__ qkv,
           const float* __restrict__ table,
           float* __restrict__ o_out) {
    constexpr int INNER = 3 * D;
    constexpr int QPB = N / QBLK;
    constexpr int NPASS = QPB / (8 * TQ);
    constexpr int TW = 2 * HH - 1;

    __shared__ float sk[D][N];
    __shared__ float sv[D][N];
    __shared__ float st[TW * TW];

    int qsec = blockIdx.x % QBLK;
    int bh   = blockIdx.x / QBLK;
    int b = bh / HEADS, h = bh % HEADS;
    const float* base = qkv + (size_t)b * 3 * INNER * N;

    const float scl = rsqrtf((float)D) * 1.4426950408889634f;

    int tid = threadIdx.x;
    for (int i = tid; i < D * (N / 4); i += 256) {
        int dd = i / (N / 4);
        int j4 = i % (N / 4);
        const float4* kr = (const float4*)(base + (size_t)(INNER + dd * HEADS + h) * N);
        const float4* vr = (const float4*)(base + (size_t)(2 * INNER + dd * HEADS + h) * N);
        ((float4*)&sk[dd][0])[j4] = kr[j4];
        ((float4*)&sv[dd][0])[j4] = vr[j4];
    }
    for (int i = tid; i < TW * TW; i += 256)
        st[i] = table[i * HEADS + h] * scl;
    __syncthreads();

    int warp = tid >> 5, lane = tid & 31;

    for (int pass = 0; pass < NPASS; pass++) {
        int q0 = qsec * QPB + (pass * 8 + warp) * TQ;

        unsigned long long qd[TQ][D];
        int At[TQ];
        #pragma unroll
        for (int t = 0; t < TQ; t++) {
            int q = q0 + t;
            #pragma unroll
            for (int dd = 0; dd < D; dd++) {
                float qv = base[(dd * HEADS + h) * N + q] * scl;
                qd[t][dd] = pk2(qv, qv);
            }
            int yq = q / HH, xq = q % HH;
            At[t] = (yq + HH - 1) * TW + xq + HH - 1;
        }

        unsigned long long l2[TQ];
        unsigned long long acc[TQ][D];
        #pragma unroll
        for (int t = 0; t < TQ; t++) {
            l2[t] = 0ull;
            #pragma unroll
            for (int dd = 0; dd < D; dd++) acc[t][dd] = 0ull;
        }

        for (int c0 = 0; c0 < N; c0 += 64) {
            int j  = c0 + lane * 2;
            int yk = j / HH, xk = j % HH;     // j even, HH even -> pair shares row
            int off = yk * TW + xk;

            unsigned long long p2[TQ];
            if constexpr (TQ > 1) {
                unsigned long long k2[D];
                #pragma unroll
                for (int dd = 0; dd < D; dd++)
                    k2[dd] = *(const unsigned long long*)&sk[dd][j];
                #pragma unroll
                for (int t = 0; t < TQ; t++) {
                    int ri = At[t] - off;
                    unsigned long long sc = pk2(st[ri], st[ri - 1]);
                    #pragma unroll
                    for (int dd = 0; dd < D; dd++)
                        sc = fma2(qd[t][dd], k2[dd], sc);
                    float a, bb; upk2(sc, a, bb);
                    p2[t] = pk2(ex2f(a), ex2f(bb));
                    l2[t] = add2(l2[t], p2[t]);
                }
                unsigned long long v2[D];
                #pragma unroll
                for (int dd = 0; dd < D; dd++)
                    v2[dd] = *(const unsigned long long*)&sv[dd][j];
                #pragma unroll
                for (int t = 0; t < TQ; t++) {
                    #pragma unroll
                    for (int dd = 0; dd < D; dd++)
                        acc[t][dd] = fma2(p2[t], v2[dd], acc[t][dd]);
                }
            } else {
                int ri = At[0] - off;
                unsigned long long sc = pk2(st[ri], st[ri - 1]);
                #pragma unroll
                for (int dd = 0; dd < D; dd++)
                    sc = fma2(qd[0][dd], *(const unsigned long long*)&sk[dd][j], sc);
                float a, bb; upk2(sc, a, bb);
                p2[0] = pk2(ex2f(a), ex2f(bb));
                l2[0] = add2(l2[0], p2[0]);
                #pragma unroll
                for (int dd = 0; dd < D; dd++)
                    acc[0][dd] = fma2(p2[0], *(const unsigned long long*)&sv[dd][j], acc[0][dd]);
            }
        }

        #pragma unroll
        for (int t = 0; t < TQ; t++) {
            int q = q0 + t;
            float lx, ly; upk2(l2[t], lx, ly);
            float ls = lx + ly;
            #pragma unroll
            for (int off = 16; off; off >>= 1)
                ls += __shfl_xor_sync(0xffffffffu, ls, off);
            float inv = 1.0f / ls;
            #pragma unroll
            for (int dd = 0; dd < D; dd++) {
                float ax, ay; upk2(acc[t][dd], ax, ay);
                float a = ax + ay;
                #pragma unroll
                for (int off = 16; off; off >>= 1)
                    a += __shfl_xor_sync(0xffffffffu, a, off);
                if (lane == 0)
                    o_out[((size_t)b * INNER + dd * HEADS + h) * N + q] = a * inv;
            }
        }
    }
}

// ---------------------------------------------------------------------------
// out projection + residual (in-place on z), float4-vectorized along n
// ---------------------------------------------------------------------------
template<int INNER, int DIM, int N>
__global__ void outproj_res(const float* __restrict__ o,
                            const float* __restrict__ w,
                            const float* __restrict__ bias,
                            float* __restrict__ z) {
    int idx = blockIdx.x * blockDim.x + threadIdx.x;
    constexpr int N4 = N / 4;
    constexpr int TOTAL4 = BATCH * DIM * N4;
    if (idx >= TOTAL4) return;
    int n4 = idx % N4;
    int t  = idx / N4;
    int c = t % DIM;
    int b = t / DIM;
    float4 s = ((float4*)z)[idx];
    float bc = bias[c];
    s.x += bc; s.y += bc; s.z += bc; s.w += bc;
    const float4* ob = (const float4*)(o + (size_t)b * INNER * N);
    const float* wr = w + (size_t)c * INNER;
    #pragma unroll
    for (int i = 0; i < INNER; i++) {
        float wv = wr[i];
        float4 ov = ob[i * N4 + n4];
        s.x += wv * ov.x; s.y += wv * ov.y; s.z += wv * ov.z; s.w += wv * ov.w;
    }
    ((float4*)z)[idx] = s;
}

// ---------------------------------------------------------------------------
// stage-3 fused tail: block = b (32 blocks, 256 threads).
//   phase 1: qkv projection from z3 (computed ONCE per b)
//   phase 2: all-heads flash attention (no-max softmax)
//   phase 3: pool commuted through out-proj + residual mean + classifier
// smem: zt[64*64] | sow[64*63] | st[3*225 pad 680] | sq[189*64] | so[63*64]
// ---------------------------------------------------------------------------
__global__ void __launch_bounds__(256, 1)
stage3_fused(const float* __restrict__ z3,
             const float* __restrict__ qw,
             const float* __restrict__ qb,
             const float* __restrict__ table,
             const float* __restrict__ ow,
             const float* __restrict__ ob,
             const float* __restrict__ cw,
             const float* __restrict__ cb,
             float* __restrict__ out) {
    constexpr int D = 21, INNER = 63, N = 64, HH = 8, TW = 15;
    extern __shared__ float sm[];
    float* zt  = sm;               // 4096
    float* sow = zt + 4096;        // 4032
    float* st3 = sow + 4032;       // 675 (padded 680)
    float* sq  = st3 + 680;        // 189*64 = 12096 (even offset -> 8B aligned)
    float* so  = sq + 12096;       // 4032

    int b = blockIdx.x;
    int tid = threadIdx.x;
    const float scl = rsqrtf((float)D) * 1.4426950408889634f;

    for (int i = tid; i < 1024; i += 256)
        ((float4*)zt)[i] = ((const float4*)(z3 + (size_t)b * 4096))[i];
    for (int i = tid; i < 64 * 63; i += 256) sow[i] = ow[i];
    for (int i = tid; i < HEADS * TW * TW; i += 256) {
        int h = i / (TW * TW), r = i % (TW * TW);
        st3[h * TW * TW + r] = table[r * HEADS + h] * scl;
    }
    __syncthreads();

    // ---- phase 1: qkv projection (once) ----
    for (int i = tid; i < 189 * 64; i += 256) {
        int o = i >> 6, p = i & 63;
        float acc = qb[o];
        const float* wr = qw + o * 64;
        #pragma unroll 16
        for (int c = 0; c < 64; c++) acc += wr[c] * zt[c * 64 + p];
        sq[o * 64 + p] = acc;
    }
    __syncthreads();

    // ---- phase 2: all-heads attention (192 units / 8 warps = 24 passes) ----
    int warp = tid >> 5, lane = tid & 31;
    int j = lane * 2;
    int yk = j >> 3, xk = j & 7;
    int off = yk * TW + xk;

    for (int pass = 0; pass < 24; pass++) {
        int unit = pass * 8 + warp;
        int h = unit >> 6;
        int q = unit & 63;
        const float* sth = st3 + h * TW * TW;

        unsigned long long qd[D];
        #pragma unroll
        for (int dd = 0; dd < D; dd++) {
            float qv = sq[(dd * HEADS + h) * N + q] * scl;
            qd[dd] = pk2(qv, qv);
        }
        int yq = q >> 3, xq = q & 7;
        int At = (yq + HH - 1) * TW + xq + HH - 1;
        int ri = At - off;

        unsigned long long sc = pk2(sth[ri], sth[ri - 1]);
        #pragma unroll
        for (int dd = 0; dd < D; dd++)
            sc = fma2(qd[dd], *(const unsigned long long*)&sq[(INNER + dd * HEADS + h) * N + j], sc);
        float a, bb; upk2(sc, a, bb);
        unsigned long long p2 = pk2(ex2f(a), ex2f(bb));

        unsigned long long acc[D];
        #pragma unroll
        for (int dd = 0; dd < D; dd++)
            acc[dd] = fma2(p2, *(const unsigned long long*)&sq[(2 * INNER + dd * HEADS + h) * N + j], pk2(0.0f, 0.0f));

        float lx, ly; upk2(p2, lx, ly);
        float ls = lx + ly;
        #pragma unroll
        for (int o2 = 16; o2; o2 >>= 1)
            ls += __shfl_xor_sync(0xffffffffu, ls, o2);
        float inv = 1.0f / ls;
        #pragma unroll
        for (int dd = 0; dd < D; dd++) {
            float ax, ay; upk2(acc[dd], ax, ay);
            float av = ax + ay;
            #pragma unroll
            for (int o2 = 16; o2; o2 >>= 1)
                av += __shfl_xor_sync(0xffffffffu, av, o2);
            if (lane == 0)
                so[(dd * HEADS + h) * N + q] = av * inv;
        }
    }
    __syncthreads();

    // ---- phase 3: pool (commuted) + out-proj + residual + classifier ----
    float* obar = sq;          // reuse: 63
    float* zbar = sq + 64;     // 64
    float* m    = sq + 128;    // 64

    if (tid < 63) {
        float s = 0.0f;
        #pragma unroll
        for (int n = 0; n < 64; n++) s += so[tid * 64 + n];
        obar[tid] = s * (1.0f / 64.0f);
    } else if (tid >= 64 && tid < 128) {
        int c = tid - 64;
        float s = 0.0f;
        #pragma unroll
        for (int n = 0; n < 64; n++) s += zt[c * 64 + n];
        zbar[c] = s * (1.0f / 64.0f);
    }
    __syncthreads();

    if (tid < 64) {
        float s = ob[tid] + zbar[tid];
        const float* wr = sow + tid * 63;
        #pragma unroll
        for (int i = 0; i < 63; i++) s += wr[i] * obar[i];
        m[tid] = s;
        out[b * 64 + tid] = s;
    }
    __syncthreads();

    if (tid < 10) {
        float t = cb[tid];
        #pragma unroll
        for (int k = 0; k < 64; k++) t += cw[tid * 64 + k] * m[k];
        out[BATCH * 64 + b * 10 + tid] = t;
    }
}

// ---------------------------------------------------------------------------

static inline int blocks(int total, int tpb) { return (total + tpb - 1) / tpb; }

extern "C" void kernel_launch(void* const* d_in, const int* in_sizes, int n_in,
                              void* d_out, int out_size) {
    const float* x       = (const float*)d_in[0];
    const float* conv1_w = (const float*)d_in[1];
    const float* conv1_b = (const float*)d_in[2];
    const float* qkv1_w  = (const float*)d_in[3];
    const float* qkv1_b  = (const float*)d_in[4];
    const float* out1_w  = (const float*)d_in[5];
    const float* out1_b  = (const float*)d_in[6];
    const float* rel1    = (const float*)d_in[7];
    const float* conv2_w = (const float*)d_in[8];
    const float* conv2_b = (const float*)d_in[9];
    const float* qkv2_w  = (const float*)d_in[10];
    const float* qkv2_b  = (const float*)d_in[11];
    const float* out2_w  = (const float*)d_in[12];
    const float* out2_b  = (const float*)d_in[13];
    const float* rel2    = (const float*)d_in[14];
    const float* conv3_w = (const float*)d_in[15];
    const float* conv3_b = (const float*)d_in[16];
    const float* qkv3_w  = (const float*)d_in[17];
    const float* qkv3_b  = (const float*)d_in[18];
    const float* out3_w  = (const float*)d_in[19];
    const float* out3_b  = (const float*)d_in[20];
    const float* rel3    = (const float*)d_in[21];
    const float* cls_w   = (const float*)d_in[22];
    const float* cls_b   = (const float*)d_in[23];
    float* out = (float*)d_out;

    float *z1, *z2, *z3, *qkv, *att;
    cudaGetSymbolAddress((void**)&z1,  g_z1);
    cudaGetSymbolAddress((void**)&z2,  g_z2);
    cudaGetSymbolAddress((void**)&z3,  g_z3);
    cudaGetSymbolAddress((void**)&qkv, g_qkv);
    cudaGetSymbolAddress((void**)&att, g_att);

    const int TPB = 256;

    constexpr int CS1 = 1 * 9 * 16 * 4;      // 576 B
    constexpr int CS2 = 16 * 9 * 32 * 4;     // 18432 B
    constexpr int CS3 = 32 * 9 * 64 * 4;     // 73728 B
    constexpr int SM3F = (4096 + 4032 + 680 + 12096 + 4032) * 4;  // 99744 B

    cudaFuncSetAttribute((const void*)conv_v3<32, 64, 16, 8, 2, 1>,
                         cudaFuncAttributeMaxDynamicSharedMemorySize, CS3);
    cudaFuncSetAttribute((const void*)stage3_fused,
                         cudaFuncAttributeMaxDynamicSharedMemorySize, SM3F);

    // ---- stage 1: N=1024, C=16, d=5 ----
    conv_v3<1, 16, 64, 32, 2, 2><<<BATCH*8*32*16/256, 256, CS1>>>(x, conv1_w, conv1_b, z1);
    proj1x1<16, 45, 1024><<<blocks(BATCH*45*256, TPB), TPB>>>(z1, qkv1_w, qkv1_b, qkv);
    attn_flash<1024, 5, 32, 8, 4><<<BATCH*HEADS*8, 256>>>(qkv, rel1, att);
    outproj_res<15, 16, 1024><<<blocks(BATCH*16*256, TPB), TPB>>>(att, out1_w, out1_b, z1);

    // ---- stage 2: N=256, C=32, d=10 ----
    conv_v3<16, 32, 32, 16, 2, 1><<<BATCH*16*16*16/256, 256, CS2>>>(z1, conv2_w, conv2_b, z2);
    proj1x1<32, 90, 256><<<blocks(BATCH*90*64, TPB), TPB>>>(z2, qkv2_w, qkv2_b, qkv);
    attn_flash<256, 10, 16, 2, 2><<<BATCH*HEADS*2, 256>>>(qkv, rel2, att);
    outproj_res<30, 32, 256><<<blocks(BATCH*32*64, TPB), TPB>>>(att, out2_w, out2_b, z2);

    // ---- stage 3: N=64, C=64, d=21 ----
    conv_v3<32, 64, 16, 8, 2, 1><<<BATCH*32*8*8/256, 256, CS3>>>(z2, conv3_w, conv3_b, z3);
    stage3_fused<<<BATCH, 256, SM3F>>>(z3, qkv3_w, qkv3_b, rel3,
                                       out3_w, out3_b, cls_w, cls_b, out);
}

// round 11
// speedup vs baseline: 1.1661x; 1.1661x over previous
#include <cuda_runtime.h>
#include <cuda_bf16.h>
#include <cstdint>

// ---------------------------------------------------------------------------
// MTL2d_DeepSVDD: 3x (conv s2 + relu -> MHSA(relpos bias) + residual) -> pool -> linear
// B=32, heads=3, dims {16,32,64}, dh {5,10,21}, inner {15,30,63}, N {1024,256,64}
// 12 launches (round-8 structure) with conv_v3 (higher-parallelism conv).
// ---------------------------------------------------------------------------

#define BATCH 32
#define HEADS 3

__device__ float g_z1[BATCH * 16 * 32 * 32];
__device__ float g_z2[BATCH * 32 * 16 * 16];
__device__ float g_z3[BATCH * 64 * 8 * 8];
__device__ float g_qkv[BATCH * 45 * 1024];
__device__ float g_att[BATCH * 15 * 1024];

// ---------------- packed f32x2 helpers --------------------------------------
__device__ __forceinline__ unsigned long long pk2(float x, float y) {
    unsigned long long r;
    asm("mov.b64 %0, {%1, %2};" : "=l"(r) : "f"(x), "f"(y));
    return r;
}
__device__ __forceinline__ void upk2(unsigned long long v, float& x, float& y) {
    asm("mov.b64 {%0, %1}, %2;" : "=f"(x), "=f"(y) : "l"(v));
}
__device__ __forceinline__ unsigned long long fma2(unsigned long long a,
                                                   unsigned long long b,
                                                   unsigned long long c) {
    unsigned long long d;
    asm("fma.rn.f32x2 %0, %1, %2, %3;" : "=l"(d) : "l"(a), "l"(b), "l"(c));
    return d;
}
__device__ __forceinline__ unsigned long long add2(unsigned long long a,
                                                   unsigned long long b) {
    unsigned long long d;
    asm("add.rn.f32x2 %0, %1, %2;" : "=l"(d) : "l"(a), "l"(b));
    return d;
}
__device__ __forceinline__ float ex2f(float x) {
    float y;
    asm("ex2.approx.ftz.f32 %0, %1;" : "=f"(y) : "f"(x));
    return y;
}

// ---------------------------------------------------------------------------
// conv 3x3 stride-2 pad-1 + bias + relu, v3: CPT channels x OXPT pixels per
// thread. Weights repacked [ci*9+k][co] in smem; packed fma2.
// ---------------------------------------------------------------------------
template<int CIN, int COUT, int HIN, int HOUT, int CPT, int OXPT>
__global__ void __launch_bounds__(256)
conv_v3(const float* __restrict__ x,
        const float* __restrict__ w,
        const float* __restrict__ bias,
        float* __restrict__ y) {
    extern __shared__ float sw[];   // [(CIN*9)][COUT]
    int tid = threadIdx.x;
    for (int i = tid; i < COUT * CIN * 9; i += 256) {
        int co = i / (CIN * 9);
        int r  = i % (CIN * 9);
        sw[r * COUT + co] = w[i];
    }
    __syncthreads();

    constexpr int OXG = HOUT / OXPT;
    constexpr int NCG = COUT / CPT;
    constexpr int NP  = CPT / 2;
    constexpr int NX  = 2 * OXPT + 1;

    int idx = blockIdx.x * 256 + tid;
    int oxp = idx % OXG;
    int t   = idx / OXG;
    int oy  = t % HOUT; t /= HOUT;
    int cog = t % NCG;
    int b   = t / NCG;

    int c0  = cog * CPT;
    int ox0 = oxp * OXPT;
    const float* xb = x + (size_t)b * CIN * HIN * HIN;

    unsigned long long acc[OXPT][NP];
    #pragma unroll
    for (int u = 0; u < OXPT; u++)
        #pragma unroll
        for (int p = 0; p < NP; p++)
            acc[u][p] = pk2(bias[c0 + 2 * p], bias[c0 + 2 * p + 1]);

    int ixb = ox0 * 2 - 1;

    for (int ci = 0; ci < CIN; ci++) {
        #pragma unroll
        for (int ky = 0; ky < 3; ky++) {
            int iy = oy * 2 - 1 + ky;
            if ((unsigned)iy >= (unsigned)HIN) continue;
            const float* row = xb + (ci * HIN + iy) * HIN;
            float xv[NX];
            #pragma unroll
            for (int u = 0; u < NX; u++) {
                int ix = ixb + u;
                xv[u] = ((unsigned)ix < (unsigned)HIN) ? row[ix] : 0.0f;
            }
            const float* wp = &sw[(ci * 9 + ky * 3) * COUT + c0];
            #pragma unroll
            for (int kx = 0; kx < 3; kx++) {
                #pragma unroll
                for (int p = 0; p < NP; p++) {
                    unsigned long long wv = *(const unsigned long long*)(wp + kx * COUT + 2 * p);
                    #pragma unroll
                    for (int u = 0; u < OXPT; u++) {
                        unsigned long long x2 = pk2(xv[kx + 2 * u], xv[kx + 2 * u]);
                        acc[u][p] = fma2(x2, wv, acc[u][p]);
                    }
                }
            }
        }
    }

    float vch[CPT][OXPT];
    #pragma unroll
    for (int u = 0; u < OXPT; u++)
        #pragma unroll
        for (int p = 0; p < NP; p++)
            upk2(acc[u][p], vch[2 * p][u], vch[2 * p + 1][u]);

    #pragma unroll
    for (int r = 0; r < CPT; r++) {
        size_t o = (((size_t)b * COUT + c0 + r) * HOUT + oy) * HOUT + ox0;
        if (OXPT == 2) {
            float2 st2 = make_float2(fmaxf(vch[r][0], 0.0f), fmaxf(vch[r][1], 0.0f));
            *(float2*)(y + o) = st2;
        } else {
            y[o] = fmaxf(vch[r][0], 0.0f);
        }
    }
}

// ---------------------------------------------------------------------------
// 1x1 projection, float4-vectorized along n
// ---------------------------------------------------------------------------
template<int C, int O, int N>
__global__ void proj1x1(const float* __restrict__ z,
                        const float* __restrict__ w,
                        const float* __restrict__ bias,
                        float* __restrict__ y) {
    int idx = blockIdx.x * blockDim.x + threadIdx.x;
    constexpr int N4 = N / 4;
    constexpr int TOTAL4 = BATCH * O * N4;
    if (idx >= TOTAL4) return;
    int n4 = idx % N4;
    int t  = idx / N4;
    int o = t % O;
    int b = t / O;
    float bo = bias[o];
    float4 s = make_float4(bo, bo, bo, bo);
    const float4* zb = (const float4*)(z + (size_t)b * C * N);
    const float* wr = w + (size_t)o * C;
    #pragma unroll
    for (int c = 0; c < C; c++) {
        float wv = wr[c];
        float4 zv = zb[c * N4 + n4];
        s.x += wv * zv.x; s.y += wv * zv.y; s.z += wv * zv.z; s.w += wv * zv.w;
    }
    ((float4*)y)[idx] = s;
}

// ---------------------------------------------------------------------------
// flash attention, NO-MAX single-pass softmax (scores provably tiny for this
// model; exp2 without max-subtraction is exact softmax here).
// block = (b, h, q-slice). K,V + de-headed pre-scaled bias table in SMEM.
// ---------------------------------------------------------------------------
template<int N, int D, int HH, int QBLK, int TQ>
__global__ void __launch_bounds__(256, 2)
attn_flash(const float* __restrict__ qkv,
           const float* __restrict__ table,
           float* __restrict__ o_out) {
    constexpr int INNER = 3 * D;
    constexpr int QPB = N / QBLK;
    constexpr int NPASS = QPB / (8 * TQ);
    constexpr int TW = 2 * HH - 1;

    __shared__ float sk[D][N];
    __shared__ float sv[D][N];
    __shared__ float st[TW * TW];

    int qsec = blockIdx.x % QBLK;
    int bh   = blockIdx.x / QBLK;
    int b = bh / HEADS, h = bh % HEADS;
    const float* base = qkv + (size_t)b * 3 * INNER * N;

    const float scl = rsqrtf((float)D) * 1.4426950408889634f;

    int tid = threadIdx.x;
    for (int i = tid; i < D * (N / 4); i += 256) {
        int dd = i / (N / 4);
        int j4 = i % (N / 4);
        const float4* kr = (const float4*)(base + (size_t)(INNER + dd * HEADS + h) * N);
        const float4* vr = (const float4*)(base + (size_t)(2 * INNER + dd * HEADS + h) * N);
        ((float4*)&sk[dd][0])[j4] = kr[j4];
        ((float4*)&sv[dd][0])[j4] = vr[j4];
    }
    for (int i = tid; i < TW * TW; i += 256)
        st[i] = table[i * HEADS + h] * scl;
    __syncthreads();

    int warp = tid >> 5, lane = tid & 31;

    for (int pass = 0; pass < NPASS; pass++) {
        int q0 = qsec * QPB + (pass * 8 + warp) * TQ;

        unsigned long long qd[TQ][D];
        int At[TQ];
        #pragma unroll
        for (int t = 0; t < TQ; t++) {
            int q = q0 + t;
            #pragma unroll
            for (int dd = 0; dd < D; dd++) {
                float qv = base[(dd * HEADS + h) * N + q] * scl;
                qd[t][dd] = pk2(qv, qv);
            }
            int yq = q / HH, xq = q % HH;
            At[t] = (yq + HH - 1) * TW + xq + HH - 1;
        }

        unsigned long long l2[TQ];
        unsigned long long acc[TQ][D];
        #pragma unroll
        for (int t = 0; t < TQ; t++) {
            l2[t] = 0ull;
            #pragma unroll
            for (int dd = 0; dd < D; dd++) acc[t][dd] = 0ull;
        }

        for (int c0 = 0; c0 < N; c0 += 64) {
            int j  = c0 + lane * 2;
            int yk = j / HH, xk = j % HH;     // j even, HH even -> pair shares row
            int off = yk * TW + xk;

            unsigned long long p2[TQ];
            if constexpr (TQ > 1) {
                unsigned long long k2[D];
                #pragma unroll
                for (int dd = 0; dd < D; dd++)
                    k2[dd] = *(const unsigned long long*)&sk[dd][j];
                #pragma unroll
                for (int t = 0; t < TQ; t++) {
                    int ri = At[t] - off;
                    unsigned long long sc = pk2(st[ri], st[ri - 1]);
                    #pragma unroll
                    for (int dd = 0; dd < D; dd++)
                        sc = fma2(qd[t][dd], k2[dd], sc);
                    float a, bb; upk2(sc, a, bb);
                    p2[t] = pk2(ex2f(a), ex2f(bb));
                    l2[t] = add2(l2[t], p2[t]);
                }
                unsigned long long v2[D];
                #pragma unroll
                for (int dd = 0; dd < D; dd++)
                    v2[dd] = *(const unsigned long long*)&sv[dd][j];
                #pragma unroll
                for (int t = 0; t < TQ; t++) {
                    #pragma unroll
                    for (int dd = 0; dd < D; dd++)
                        acc[t][dd] = fma2(p2[t], v2[dd], acc[t][dd]);
                }
            } else {
                int ri = At[0] - off;
                unsigned long long sc = pk2(st[ri], st[ri - 1]);
                #pragma unroll
                for (int dd = 0; dd < D; dd++)
                    sc = fma2(qd[0][dd], *(const unsigned long long*)&sk[dd][j], sc);
                float a, bb; upk2(sc, a, bb);
                p2[0] = pk2(ex2f(a), ex2f(bb));
                l2[0] = add2(l2[0], p2[0]);
                #pragma unroll
                for (int dd = 0; dd < D; dd++)
                    acc[0][dd] = fma2(p2[0], *(const unsigned long long*)&sv[dd][j], acc[0][dd]);
            }
        }

        #pragma unroll
        for (int t = 0; t < TQ; t++) {
            int q = q0 + t;
            float lx, ly; upk2(l2[t], lx, ly);
            float ls = lx + ly;
            #pragma unroll
            for (int off = 16; off; off >>= 1)
                ls += __shfl_xor_sync(0xffffffffu, ls, off);
            float inv = 1.0f / ls;
            #pragma unroll
            for (int dd = 0; dd < D; dd++) {
                float ax, ay; upk2(acc[t][dd], ax, ay);
                float a = ax + ay;
                #pragma unroll
                for (int off = 16; off; off >>= 1)
                    a += __shfl_xor_sync(0xffffffffu, a, off);
                if (lane == 0)
                    o_out[((size_t)b * INNER + dd * HEADS + h) * N + q] = a * inv;
            }
        }
    }
}

// ---------------------------------------------------------------------------
// out projection + residual (in-place on z), float4-vectorized along n
// ---------------------------------------------------------------------------
template<int INNER, int DIM, int N>
__global__ void outproj_res(const float* __restrict__ o,
                            const float* __restrict__ w,
                            const float* __restrict__ bias,
                            float* __restrict__ z) {
    int idx = blockIdx.x * blockDim.x + threadIdx.x;
    constexpr int N4 = N / 4;
    constexpr int TOTAL4 = BATCH * DIM * N4;
    if (idx >= TOTAL4) return;
    int n4 = idx % N4;
    int t  = idx / N4;
    int c = t % DIM;
    int b = t / DIM;
    float4 s = ((float4*)z)[idx];
    float bc = bias[c];
    s.x += bc; s.y += bc; s.z += bc; s.w += bc;
    const float4* ob = (const float4*)(o + (size_t)b * INNER * N);
    const float* wr = w + (size_t)c * INNER;
    #pragma unroll
    for (int i = 0; i < INNER; i++) {
        float wv = wr[i];
        float4 ov = ob[i * N4 + n4];
        s.x += wv * ov.x; s.y += wv * ov.y; s.z += wv * ov.z; s.w += wv * ov.w;
    }
    ((float4*)z)[idx] = s;
}

// ---------------------------------------------------------------------------
// stage-3 tail: pooling commuted through out-proj, then classifier.
// ---------------------------------------------------------------------------
__global__ void outproj_pool_cls(const float* __restrict__ o,
                                 const float* __restrict__ w,
                                 const float* __restrict__ ob,
                                 const float* __restrict__ z3,
                                 const float* __restrict__ cw,
                                 const float* __restrict__ cb,
                                 float* __restrict__ out) {
    int b = blockIdx.x;
    int tid = threadIdx.x;   // 128 threads
    __shared__ float obar[63];
    __shared__ float zbar[64];
    __shared__ float m[64];

    if (tid < 63) {
        const float* op = o + ((size_t)b * 63 + tid) * 64;
        float s = 0.0f;
        #pragma unroll
        for (int n = 0; n < 64; n++) s += op[n];
        obar[tid] = s * (1.0f / 64.0f);
    } else if (tid >= 64) {
        int c = tid - 64;
        const float* zp = z3 + ((size_t)b * 64 + c) * 64;
        float s = 0.0f;
        #pragma unroll
        for (int n = 0; n < 64; n++) s += zp[n];
        zbar[c] = s * (1.0f / 64.0f);
    }
    __syncthreads();

    if (tid < 64) {
        float s = ob[tid] + zbar[tid];
        const float* wr = w + tid * 63;
        #pragma unroll
        for (int i = 0; i < 63; i++) s += wr[i] * obar[i];
        m[tid] = s;
        out[b * 64 + tid] = s;
    }
    __syncthreads();

    if (tid < 10) {
        float t = cb[tid];
        #pragma unroll
        for (int k = 0; k < 64; k++) t += cw[tid * 64 + k] * m[k];
        out[BATCH * 64 + b * 10 + tid] = t;
    }
}

// ---------------------------------------------------------------------------

static inline int blocks(int total, int tpb) { return (total + tpb - 1) / tpb; }

extern "C" void kernel_launch(void* const* d_in, const int* in_sizes, int n_in,
                              void* d_out, int out_size) {
    const float* x       = (const float*)d_in[0];
    const float* conv1_w = (const float*)d_in[1];
    const float* conv1_b = (const float*)d_in[2];
    const float* qkv1_w  = (const float*)d_in[3];
    const float* qkv1_b  = (const float*)d_in[4];
    const float* out1_w  = (const float*)d_in[5];
    const float* out1_b  = (const float*)d_in[6];
    const float* rel1    = (const float*)d_in[7];
    const float* conv2_w = (const float*)d_in[8];
    const float* conv2_b = (const float*)d_in[9];
    const float* qkv2_w  = (const float*)d_in[10];
    const float* qkv2_b  = (const float*)d_in[11];
    const float* out2_w  = (const float*)d_in[12];
    const float* out2_b  = (const float*)d_in[13];
    const float* rel2    = (const float*)d_in[14];
    const float* conv3_w = (const float*)d_in[15];
    const float* conv3_b = (const float*)d_in[16];
    const float* qkv3_w  = (const float*)d_in[17];
    const float* qkv3_b  = (const float*)d_in[18];
    const float* out3_w  = (const float*)d_in[19];
    const float* out3_b  = (const float*)d_in[20];
    const float* rel3    = (const float*)d_in[21];
    const float* cls_w   = (const float*)d_in[22];
    const float* cls_b   = (const float*)d_in[23];
    float* out = (float*)d_out;

    float *z1, *z2, *z3, *qkv, *att;
    cudaGetSymbolAddress((void**)&z1,  g_z1);
    cudaGetSymbolAddress((void**)&z2,  g_z2);
    cudaGetSymbolAddress((void**)&z3,  g_z3);
    cudaGetSymbolAddress((void**)&qkv, g_qkv);
    cudaGetSymbolAddress((void**)&att, g_att);

    const int TPB = 256;

    constexpr int CS1 = 1 * 9 * 16 * 4;      // 576 B
    constexpr int CS2 = 16 * 9 * 32 * 4;     // 18432 B
    constexpr int CS3 = 32 * 9 * 64 * 4;     // 73728 B
    cudaFuncSetAttribute((const void*)conv_v3<32, 64, 16, 8, 2, 1>,
                         cudaFuncAttributeMaxDynamicSharedMemorySize, CS3);

    // ---- stage 1: N=1024, C=16, d=5 ----
    conv_v3<1, 16, 64, 32, 2, 2><<<BATCH*8*32*16/256, 256, CS1>>>(x, conv1_w, conv1_b, z1);
    proj1x1<16, 45, 1024><<<blocks(BATCH*45*256, TPB), TPB>>>(z1, qkv1_w, qkv1_b, qkv);
    attn_flash<1024, 5, 32, 8, 4><<<BATCH*HEADS*8, 256>>>(qkv, rel1, att);
    outproj_res<15, 16, 1024><<<blocks(BATCH*16*256, TPB), TPB>>>(att, out1_w, out1_b, z1);

    // ---- stage 2: N=256, C=32, d=10 ----
    conv_v3<16, 32, 32, 16, 2, 1><<<BATCH*16*16*16/256, 256, CS2>>>(z1, conv2_w, conv2_b, z2);
    proj1x1<32, 90, 256><<<blocks(BATCH*90*64, TPB), TPB>>>(z2, qkv2_w, qkv2_b, qkv);
    attn_flash<256, 10, 16, 2, 2><<<BATCH*HEADS*2, 256>>>(qkv, rel2, att);
    outproj_res<30, 32, 256><<<blocks(BATCH*32*64, TPB), TPB>>>(att, out2_w, out2_b, z2);

    // ---- stage 3: N=64, C=64, d=21 ----
    conv_v3<32, 64, 16, 8, 2, 1><<<BATCH*32*8*8/256, 256, CS3>>>(z2, conv3_w, conv3_b, z3);
    proj1x1<64, 189, 64><<<blocks(BATCH*189*16, TPB), TPB>>>(z3, qkv3_w, qkv3_b, qkv);
    attn_flash<64, 21, 8, 1, 1><<<BATCH*HEADS, 256>>>(qkv, rel3, att);

    // ---- fused stage-3 out-proj + pool + classifier ----
    outproj_pool_cls<<<BATCH, 128>>>(att, out3_w, out3_b, z3, cls_w, cls_b, out);
}